// round 1
// baseline (speedup 1.0000x reference)
#include <cuda_runtime.h>
#include <cstdint>

// PARAFAC / CP reconstruction: out[a,b,c] = sum_k f0[k,a] * f1[k,b] * f2[k,c]
// A = B = C = 512, RANK = 16, all fp32.
//
// Strategy: block = (one a, 64-b chunk, full 512-c row).
//   - thread owns c-pair (c0, c0+1); f2[k][c-pair] held in 16 packed-f32x2 regs (loaded once)
//   - g[k][b] = f0[k,a]*f1[k,b] precomputed, SPLATTED into shared as f32x2 pairs
//   - inner loop per b: 8x LDS.128 (broadcast) + 16x fma.rn.f32x2 (4 acc chains) + 1x STG.64
// Kernel is HBM-store-bound (536 MB output); packed FFMA2 keeps compute under the store floor.

#define A_DIM 512
#define B_DIM 512
#define C_DIM 512
#define RANK  16
#define BCHUNK 64
#define NTHREADS 256

typedef unsigned long long ull;

__global__ __launch_bounds__(NTHREADS, 4)
void parafac_kernel(const float* __restrict__ f0,
                    const float* __restrict__ f1,
                    const float* __restrict__ f2,
                    float* __restrict__ out)
{
    // g splatted: gsh[j][k] = pack(g, g) where g = f0[k][a] * f1[k][b0+j]
    __shared__ __align__(16) ull gsh[BCHUNK][RANK];

    const int a  = blockIdx.y;
    const int b0 = blockIdx.x * BCHUNK;
    const int t  = threadIdx.x;
    const int c0 = t * 2;   // thread's fixed c-pair

    // ---- load f2[k][c0..c0+1] into packed registers (once per block) ----
    ull f2r[RANK];
#pragma unroll
    for (int k = 0; k < RANK; k++) {
        f2r[k] = *reinterpret_cast<const ull*>(f2 + k * C_DIM + c0);
    }

    // ---- precompute g, splatted to f32x2 ----
    // BCHUNK*RANK = 1024 entries, 256 threads -> 4 each
#pragma unroll
    for (int i = 0; i < (BCHUNK * RANK) / NTHREADS; i++) {
        int idx = t + i * NTHREADS;
        int j = idx >> 4;     // b offset within chunk
        int k = idx & 15;     // rank index
        float v = f0[k * A_DIM + a] * f1[k * B_DIM + b0 + j];
        float2 p = make_float2(v, v);
        gsh[j][k] = *reinterpret_cast<ull*>(&p);
    }
    __syncthreads();

    float* orow = out + (size_t)a * (B_DIM * C_DIM) + (size_t)b0 * C_DIM + c0;

#pragma unroll 2
    for (int j = 0; j < BCHUNK; j++) {
        const ulonglong2* gjv = reinterpret_cast<const ulonglong2*>(gsh[j]);

        ull acc0 = 0ull, acc1 = 0ull, acc2 = 0ull, acc3 = 0ull; // 0x0 == (0.0f, 0.0f)

#pragma unroll
        for (int kk = 0; kk < RANK / 4; kk++) {
            ulonglong2 ga = gjv[2 * kk + 0];   // g[4kk], g[4kk+1]
            ulonglong2 gb = gjv[2 * kk + 1];   // g[4kk+2], g[4kk+3]
            asm("fma.rn.f32x2 %0, %1, %2, %0;" : "+l"(acc0) : "l"(f2r[4 * kk + 0]), "l"(ga.x));
            asm("fma.rn.f32x2 %0, %1, %2, %0;" : "+l"(acc1) : "l"(f2r[4 * kk + 1]), "l"(ga.y));
            asm("fma.rn.f32x2 %0, %1, %2, %0;" : "+l"(acc2) : "l"(f2r[4 * kk + 2]), "l"(gb.x));
            asm("fma.rn.f32x2 %0, %1, %2, %0;" : "+l"(acc3) : "l"(f2r[4 * kk + 3]), "l"(gb.y));
        }

        ull s0, s1, r;
        asm("add.rn.f32x2 %0, %1, %2;" : "=l"(s0) : "l"(acc0), "l"(acc1));
        asm("add.rn.f32x2 %0, %1, %2;" : "=l"(s1) : "l"(acc2), "l"(acc3));
        asm("add.rn.f32x2 %0, %1, %2;" : "=l"(r)  : "l"(s0),   "l"(s1));

        *reinterpret_cast<ull*>(orow + (size_t)j * C_DIM) = r;
    }
}

extern "C" void kernel_launch(void* const* d_in, const int* in_sizes, int n_in,
                              void* d_out, int out_size)
{
    const float* f0 = (const float*)d_in[0];
    const float* f1 = (const float*)d_in[1];
    const float* f2 = (const float*)d_in[2];
    float* out = (float*)d_out;

    dim3 grid(B_DIM / BCHUNK, A_DIM);   // (8, 512) = 4096 blocks
    dim3 block(NTHREADS);
    parafac_kernel<<<grid, block>>>(f0, f1, f2, out);
}

// round 2
// speedup vs baseline: 1.6170x; 1.6170x over previous
#include <cuda_runtime.h>
#include <cstdint>

// PARAFAC / CP reconstruction: out[a,b,c] = sum_k f0[k,a] * f1[k,b] * f2[k,c]
// A = B = C = 512, RANK = 16, all fp32. Output = 536 MB pure stores -> HBM-store bound.
//
// Round-2 redesign (L1 was 95.5% saturated in round 1):
//   - thread owns a c-QUAD (4 floats) -> STG.128 (minimum 1 wf / 128 B stored)
//   - g[j][k] stored UNsplatted in shared (16 floats/b = 4 LDS.128), splat to (g,g)
//     in registers via mov.b64 {r,r} (moves cost off the L1 pipe onto issue/ALU)
//   - f2[k][c-quad] held in 32 packed f32x2 registers, loaded once per block
// L1 wavefronts: 4 LDS + 4 STG per warp per 512 B stored = 2 wf/128B (was 5).

#define A_DIM 512
#define B_DIM 512
#define C_DIM 512
#define RANK  16
#define BCHUNK 64
#define NTHREADS 128   // 128 c-lanes x 4 c each = 512 c

typedef unsigned long long ull;

__global__ __launch_bounds__(NTHREADS, 4)
void parafac_kernel(const float* __restrict__ f0,
                    const float* __restrict__ f1,
                    const float* __restrict__ f2,
                    float* __restrict__ out)
{
    // plain (unsplatted) g: gsh[j][k] = f0[k][a] * f1[k][b0+j]
    __shared__ __align__(16) float gsh[BCHUNK][RANK];

    const int a  = blockIdx.y;
    const int b0 = blockIdx.x * BCHUNK;
    const int t  = threadIdx.x;
    const int c0 = t * 4;   // thread's fixed c-quad

    // ---- f2[k][c0..c0+3] as 2 packed f32x2 regs per k (loaded once) ----
    ull f2r[2 * RANK];
#pragma unroll
    for (int k = 0; k < RANK; k++) {
        ulonglong2 v = *reinterpret_cast<const ulonglong2*>(f2 + k * C_DIM + c0);
        f2r[2 * k + 0] = v.x;
        f2r[2 * k + 1] = v.y;
    }

    // ---- precompute g (plain floats): 64*16 = 1024 entries, 128 threads -> 8 each ----
#pragma unroll
    for (int i = 0; i < (BCHUNK * RANK) / NTHREADS; i++) {
        int idx = t + i * NTHREADS;
        int j = idx >> 4;     // b offset within chunk
        int k = idx & 15;     // rank index
        gsh[j][k] = f0[k * A_DIM + a] * f1[k * B_DIM + b0 + j];
    }
    __syncthreads();

    float* orow = out + (size_t)a * (B_DIM * C_DIM) + (size_t)b0 * C_DIM + c0;

#pragma unroll 2
    for (int j = 0; j < BCHUNK; j++) {
        // 4x LDS.128 (broadcast across the warp)
        const float4* gj = reinterpret_cast<const float4*>(gsh[j]);
        float4 q0 = gj[0], q1 = gj[1], q2 = gj[2], q3 = gj[3];
        float gf[RANK] = { q0.x, q0.y, q0.z, q0.w,
                           q1.x, q1.y, q1.z, q1.w,
                           q2.x, q2.y, q2.z, q2.w,
                           q3.x, q3.y, q3.z, q3.w };

        // two independent accumulator chains per c-pair (k even / k odd)
        ull a0 = 0ull, a1 = 0ull;   // chains for c-pair 0
        ull b0r = 0ull, b1r = 0ull; // chains for c-pair 1

#pragma unroll
        for (int k = 0; k < RANK; k += 2) {
            ull gp0, gp1;
            asm("mov.b64 %0, {%1,%1};" : "=l"(gp0) : "r"(__float_as_uint(gf[k])));
            asm("mov.b64 %0, {%1,%1};" : "=l"(gp1) : "r"(__float_as_uint(gf[k + 1])));
            asm("fma.rn.f32x2 %0, %1, %2, %0;" : "+l"(a0)  : "l"(f2r[2 * k + 0]), "l"(gp0));
            asm("fma.rn.f32x2 %0, %1, %2, %0;" : "+l"(b0r) : "l"(f2r[2 * k + 1]), "l"(gp0));
            asm("fma.rn.f32x2 %0, %1, %2, %0;" : "+l"(a1)  : "l"(f2r[2 * k + 2]), "l"(gp1));
            asm("fma.rn.f32x2 %0, %1, %2, %0;" : "+l"(b1r) : "l"(f2r[2 * k + 3]), "l"(gp1));
        }

        ulonglong2 r;
        asm("add.rn.f32x2 %0, %1, %2;" : "=l"(r.x) : "l"(a0),  "l"(a1));
        asm("add.rn.f32x2 %0, %1, %2;" : "=l"(r.y) : "l"(b0r), "l"(b1r));

        // STG.128, warp covers 512 contiguous bytes
        *reinterpret_cast<ulonglong2*>(orow + (size_t)j * C_DIM) = r;
    }
}

extern "C" void kernel_launch(void* const* d_in, const int* in_sizes, int n_in,
                              void* d_out, int out_size)
{
    const float* f0 = (const float*)d_in[0];
    const float* f1 = (const float*)d_in[1];
    const float* f2 = (const float*)d_in[2];
    float* out = (float*)d_out;

    dim3 grid(B_DIM / BCHUNK, A_DIM);   // (8, 512) = 4096 blocks
    dim3 block(NTHREADS);
    parafac_kernel<<<grid, block>>>(f0, f1, f2, out);
}